// round 16
// baseline (speedup 1.0000x reference)
#include <cuda_runtime.h>
#include <cuda_fp16.h>
#include <cstdint>
#include <cstddef>

// ---------------------------------------------------------------------------
// FlowActionHeadPACE — round 15: R10 engine (128x128, 256 thr, BK=64, NSTG=3,
// 2 CTA/SM) + fused split-K u-update (MODE 7: in-kernel CTA handoff replaces
// the per-step finalize kernel).
//
//   cond   = concat(...) @ Wc + bc                        (once -> fp16)
//   cpre   = fp16(cond @ W1_c + b1)                       (once)
//   uadd   = dt * (p_hat @ b3)                            (once)
//   step i: h1 = silu(u @ W1_u + cpre + tau*w1_tau)       -> fp16
//           h2 = silu(h1_k @ W2_k + b2_k) * gate          -> fp16
//           u += dt*(h2 @ W3) + uadd ; uf = fp16(u)       (MODE 7, one launch)
//   out = [u @ Wd + bd , u]                               (one kernel)
// ---------------------------------------------------------------------------

#define BB      4096
#define FUSION  1024
#define COND_IN 1216
#define LATENT  512
#define NEXP    8
#define HID     1024
#define KH      8192
#define DT      0.125f

typedef __half fp16;

// ---------------- device scratch ----------------
__device__ float g_u   [(size_t)BB * LATENT];
__device__ float g_uadd[(size_t)BB * LATENT];
__device__ float g_tauv[KH];
__device__ float g_part[(size_t)BB * LATENT];       // split-K partial (z=1)
__device__ int   g_flag[128];                       // per-tile handoff flags

__device__ __align__(16) fp16 g_cpre[(size_t)BB * KH];
__device__ __align__(16) fp16 g_x  [(size_t)BB * COND_IN];
__device__ __align__(16) fp16 g_c  [(size_t)BB * FUSION];
__device__ __align__(16) fp16 g_uf [(size_t)BB * LATENT];
__device__ __align__(16) fp16 g_h1 [(size_t)BB * KH];
__device__ __align__(16) fp16 g_h2 [(size_t)BB * KH];

__device__ __align__(16) fp16 g_wct [(size_t)FUSION * COND_IN];
__device__ __align__(16) fp16 g_w1ut[(size_t)KH * LATENT];
__device__ __align__(16) fp16 g_w1ct[(size_t)KH * FUSION];
__device__ __align__(16) fp16 g_w2t [(size_t)NEXP * HID * HID];
__device__ __align__(16) fp16 g_w3t [(size_t)LATENT * KH];
__device__ __align__(16) fp16 g_wdt [(size_t)LATENT * LATENT];

// ---------------- helpers ----------------
__device__ __forceinline__ uint32_t smem_u32(const void* p) {
    uint32_t a;
    asm("{ .reg .u64 t; cvta.to.shared.u64 t, %1; cvt.u32.u64 %0, t; }" : "=r"(a) : "l"(p));
    return a;
}
__device__ __forceinline__ void cp_async16(uint32_t dst, const void* src) {
    asm volatile("cp.async.cg.shared.global [%0], [%1], 16;" :: "r"(dst), "l"(src));
}
#define CP_COMMIT() asm volatile("cp.async.commit_group;" ::: "memory")
#define CP_WAIT2()  asm volatile("cp.async.wait_group 2;" ::: "memory")

#define LDM4(r0, r1, r2, r3, addr)                                             \
    asm volatile("ldmatrix.sync.aligned.m8n8.x4.shared.b16 {%0,%1,%2,%3}, [%4];" \
        : "=r"(r0), "=r"(r1), "=r"(r2), "=r"(r3) : "r"(addr))

#define MMA16816(d, a, b0, b1)                                                \
    asm volatile("mma.sync.aligned.m16n8k16.row.col.f32.f16.f16.f32 "         \
        "{%0,%1,%2,%3}, {%4,%5,%6,%7}, {%8,%9}, {%0,%1,%2,%3};"               \
        : "+f"((d)[0]), "+f"((d)[1]), "+f"((d)[2]), "+f"((d)[3])              \
        : "r"((a)[0]), "r"((a)[1]), "r"((a)[2]), "r"((a)[3]),                 \
          "r"(b0), "r"(b1))

// ---------------------------------------------------------------------------
// HMMA GEMM: C(128x128) = epi( A[M,K] @ B[N,K]^T ), fp16 in, fp32 accum.
// 8 warps 4(M)x2(N); warp tile 32x64; BK=64; 3-stage cp.async; 2 CTAs/SM.
// MODE 0: Cf = acc + bias[c]                              (fp32 store)
// MODE 1: Ca = fp16(acc + bias[c])                        (cond / cpre)
// MODE 2: Ca = fp16(silu(acc + addm(fp16) + s1*vecc[c]))  (h1)
// MODE 3: Ca = fp16(silu(acc + bias[c]) * vecc[r*8+ke])   (h2, z=expert)
// MODE 6: Cf = acc + bias[c]; Cf[(BB+r)*ldc+cg] = vecc[...] (decode+copy)
// MODE 7: fused split-K u-update: z=1 writes partp + flag; z=0 waits, then
//         Cf(u) += DT*(acc + partp) + uaddp ; Ca(uf) = fp16(u).
// ---------------------------------------------------------------------------
#define ROWB  144                 // bytes per smem row (64 fp16 + 16B pad)
#define PLANE (128 * ROWB)        // 18432 B
#define STG   (2 * PLANE)         // A, B = 36864 B
#define NSTG  3

template <int MODE>
__global__ void __launch_bounds__(256, 2)
mma_gemm(const fp16* __restrict__ A, int lda,
         const fp16* __restrict__ B, int ldb,
         int Kdim,
         float* __restrict__ Cf, int ldc,
         fp16* __restrict__ Ca, int ldc2,
         const float* __restrict__ bias,
         const fp16* __restrict__ addm, int addld,
         const float* __restrict__ vecc, float s1,
         float* __restrict__ partp, const float* __restrict__ uaddp,
         int* __restrict__ flag, int target) {
    extern __shared__ char smem[];
    const uint32_t sbase = smem_u32(smem);
    const int tid  = threadIdx.x;
    const int wid  = tid >> 5;
    const int lane = tid & 31;
    const int wm   = wid >> 1;          // 0..3  (M)
    const int wc   = wid & 1;           // 0..1  (N)
    const int brow = blockIdx.y * 128;
    const int bcol = blockIdx.x * 128;

    int kexp = 0;
    if (MODE == 3) {
        kexp = blockIdx.z;
        A  += kexp * HID;
        B  += (size_t)kexp * HID * HID;
        Ca += kexp * HID;
        bias += kexp * HID;
    }
    int zsk = 0;
    if (MODE == 7) {
        zsk = blockIdx.z;
        A += (size_t)zsk * Kdim;        // K-window shift (lda = full K)
        B += (size_t)zsk * Kdim;
    }

    const fp16* Ap = A + (size_t)brow * lda;
    const fp16* Bp = B + (size_t)bcol * ldb;

    const int NC = Kdim >> 6;           // BK = 64

    auto load_chunk = [&](int c) {
        const uint32_t st = sbase + (c % NSTG) * STG;
        const int k0 = c << 6;
#pragma unroll
        for (int it = 0; it < 4; it++) {
            int id  = tid + it * 256;   // 0..1023
            int row = id >> 3;
            int seg = id & 7;
            uint32_t dst = st + row * ROWB + seg * 16;
            cp_async16(dst,         Ap + (size_t)row * lda + k0 + seg * 8);
            cp_async16(dst + PLANE, Bp + (size_t)row * ldb + k0 + seg * 8);
        }
        CP_COMMIT();
    };

    float acc[2][8][4];
#pragma unroll
    for (int im = 0; im < 2; im++)
#pragma unroll
        for (int jb = 0; jb < 8; jb++)
#pragma unroll
            for (int q = 0; q < 4; q++) acc[im][jb][q] = 0.f;

    load_chunk(0);
    if (NC > 1) load_chunk(1);
    if (NC > 2) load_chunk(2);

    const int lrow = lane & 15;          // ldmatrix row within 16
    const int lkhi = (lane >> 4) * 8;    // k offset 0/8

    for (int c = 0; c < NC; c++) {
        CP_WAIT2();
        __syncthreads();
        const uint32_t st = sbase + (c % NSTG) * STG;
        const uint32_t sA = st;
        const uint32_t sB = st + PLANE;

#pragma unroll
        for (int kk = 0; kk < 64; kk += 16) {
            uint32_t a[2][4];
#pragma unroll
            for (int im = 0; im < 2; im++) {
                uint32_t ad = sA + (wm * 32 + im * 16 + lrow) * ROWB + (kk + lkhi) * 2;
                LDM4(a[im][0], a[im][1], a[im][2], a[im][3], ad);
            }
#pragma unroll
            for (int jb2 = 0; jb2 < 4; jb2++) {
                uint32_t nrow = sB + (wc * 64 + jb2 * 16 + lrow) * ROWB + (kk + lkhi) * 2;
                uint32_t b0, b1, b2, b3;
                LDM4(b0, b1, b2, b3, nrow);
#pragma unroll
                for (int im = 0; im < 2; im++) {
                    MMA16816(acc[im][jb2 * 2 + 0], a[im], b0, b2);
                    MMA16816(acc[im][jb2 * 2 + 1], a[im], b1, b3);
                }
            }
        }
        __syncthreads();
        if (c + 3 < NC) load_chunk(c + 3);
    }

    // ---- epilogue ----
    const int lr  = lane >> 2;
    const int lc2 = (lane & 3) * 2;

    if (MODE == 7) {
        const int tile = blockIdx.y * gridDim.x + blockIdx.x;   // 0..127
        if (zsk == 1) {
            // producer: write partial, release flag
#pragma unroll
            for (int im = 0; im < 2; im++)
#pragma unroll
                for (int half = 0; half < 2; half++) {
                    const int r = brow + wm * 32 + im * 16 + lr + half * 8;
#pragma unroll
                    for (int jb = 0; jb < 8; jb++) {
                        const int cg = bcol + wc * 64 + jb * 8 + lc2;
                        *(float2*)(partp + (size_t)r * ldc + cg) =
                            make_float2(acc[im][jb][half * 2 + 0],
                                        acc[im][jb][half * 2 + 1]);
                    }
                }
            __syncthreads();
            __threadfence();
            if (tid == 0) atomicAdd(flag + tile, 1);
        } else {
            // consumer: wait for producer's partial, fuse u update
            if (tid == 0) {
                while (atomicAdd(flag + tile, 0) < target) { }
            }
            __syncthreads();
            __threadfence();
#pragma unroll
            for (int im = 0; im < 2; im++)
#pragma unroll
                for (int half = 0; half < 2; half++) {
                    const int r = brow + wm * 32 + im * 16 + lr + half * 8;
#pragma unroll
                    for (int jb = 0; jb < 8; jb++) {
                        const int cg = bcol + wc * 64 + jb * 8 + lc2;
                        size_t idx = (size_t)r * ldc + cg;
                        float2 pv = *(const float2*)(partp + idx);
                        float2 av = *(const float2*)(uaddp + idx);
                        float2 uo = *(const float2*)(Cf + idx);
                        float v0 = uo.x + DT * (acc[im][jb][half * 2 + 0] + pv.x) + av.x;
                        float v1 = uo.y + DT * (acc[im][jb][half * 2 + 1] + pv.y) + av.y;
                        *(float2*)(Cf + idx) = make_float2(v0, v1);
                        *(__half2*)(Ca + (size_t)r * ldc2 + cg) =
                            __halves2half2(__float2half_rn(v0), __float2half_rn(v1));
                    }
                }
        }
        return;
    }

#pragma unroll
    for (int im = 0; im < 2; im++) {
#pragma unroll
        for (int half = 0; half < 2; half++) {
            const int r = brow + wm * 32 + im * 16 + lr + half * 8;
#pragma unroll
            for (int jb = 0; jb < 8; jb++) {
                const int cg = bcol + wc * 64 + jb * 8 + lc2;
                float a0 = acc[im][jb][half * 2 + 0];
                float a1 = acc[im][jb][half * 2 + 1];
                float v0, v1;
                if (MODE == 0 || MODE == 6) {
                    v0 = a0 + bias[cg]; v1 = a1 + bias[cg + 1];
                    *(float2*)(Cf + (size_t)r * ldc + cg) = make_float2(v0, v1);
                    if (MODE == 6) {
                        float2 uv = *(const float2*)(vecc + (size_t)r * ldc + cg);
                        *(float2*)(Cf + (size_t)(BB + r) * ldc + cg) = uv;
                    }
                } else {
                    if (MODE == 1) {
                        v0 = a0 + bias[cg]; v1 = a1 + bias[cg + 1];
                    } else if (MODE == 2) {
                        __half2 ah2 = *(const __half2*)(addm + (size_t)r * addld + cg);
                        float2 ad = __half22float2(ah2);
                        v0 = a0 + ad.x + s1 * vecc[cg];
                        v1 = a1 + ad.y + s1 * vecc[cg + 1];
                        v0 = v0 / (1.f + __expf(-v0));
                        v1 = v1 / (1.f + __expf(-v1));
                    } else {  // MODE 3
                        v0 = a0 + bias[cg]; v1 = a1 + bias[cg + 1];
                        v0 = v0 / (1.f + __expf(-v0));
                        v1 = v1 / (1.f + __expf(-v1));
                        float gt = vecc[r * 8 + kexp];
                        v0 *= gt; v1 *= gt;
                    }
                    *(__half2*)(Ca + (size_t)r * ldc2 + cg) =
                        __halves2half2(__float2half_rn(v0), __float2half_rn(v1));
                }
            }
        }
    }
}

// ---------------------------------------------------------------------------
// setup kernels
// ---------------------------------------------------------------------------
__global__ void combo_setup(const float* __restrict__ fo,
                            const float* __restrict__ pe,
                            const float* __restrict__ sl,
                            const float* __restrict__ u0,
                            const float* __restrict__ p,
                            const float* __restrict__ b3,
                            const float* __restrict__ W1,
                            fp16* __restrict__ x,
                            float* __restrict__ u, fp16* __restrict__ uf,
                            float* __restrict__ uadd,
                            float* __restrict__ tv,
                            int* __restrict__ flag) {
    int i = blockIdx.x * blockDim.x + threadIdx.x;
    if (i < 128) flag[i] = 0;
    if (i < BB * COND_IN) {
        int b = i / COND_IN, j = i - b * COND_IN;
        float v;
        if (j < 1024)       v = fo[b * 1024 + j];
        else if (j < 1152)  v = pe[b * 128 + (j - 1024)];
        else                v = sl[b * 64 + (j - 1152)];
        x[i] = __float2half_rn(v);
    }
    if (i < BB * LATENT) {
        int b = i >> 9, d = i & 511;
        float v = u0[i];
        u[i] = v;
        uf[i] = __float2half_rn(v);
        float s = 0.f;
#pragma unroll
        for (int k = 0; k < NEXP; k++) s += p[b * 8 + k] * b3[k * 512 + d];
        uadd[i] = DT * s;
    }
    if (i < KH) {
        int ke = i >> 10, hcol = i & 1023;
        tv[i] = W1[((size_t)ke * 1537 + 1536) * 1024 + hcol];
    }
}

struct TJob {
    const float* in;
    fp16* out;
    long long in_es, out_es;
    int in_ld, out_ld, rows, cols, tx, ty, ntiles;
};
struct TJobs { TJob j[6]; };

__global__ void tconv_all(TJobs J) {
    __shared__ float t[32][33];
    int f = blockIdx.x;
    const TJob* job = nullptr;
    int iz = 0, ix = 0, iy = 0;
#pragma unroll
    for (int jj = 0; jj < 6; jj++) {
        if (job == nullptr) {
            if (f < J.j[jj].ntiles) {
                job = &J.j[jj];
                int per = job->tx * job->ty;
                iz = f / per;
                int rem = f - iz * per;
                ix = rem % job->tx;
                iy = rem / job->tx;
            } else {
                f -= J.j[jj].ntiles;
            }
        }
    }
    const float* in = job->in + (size_t)iz * job->in_es;
    fp16* out = job->out + (size_t)iz * job->out_es;
    const int r0 = iy * 32, c0 = ix * 32;
    const int tx = threadIdx.x, ty = threadIdx.y;      // 32 x 8
#pragma unroll
    for (int i = 0; i < 32; i += 8) {
        int r = r0 + ty + i, c = c0 + tx;
        if (r < job->rows && c < job->cols) t[ty + i][tx] = in[(size_t)r * job->in_ld + c];
    }
    __syncthreads();
#pragma unroll
    for (int i = 0; i < 32; i += 8) {
        int c = c0 + ty + i, r = r0 + tx;
        if (c < job->cols && r < job->rows)
            out[(size_t)c * job->out_ld + r] = __float2half_rn(t[tx][ty + i]);
    }
}

// ---------------------------------------------------------------------------
extern "C" void kernel_launch(void* const* d_in, const int* in_sizes, int n_in,
                              void* d_out, int out_size) {
    const float* fused = (const float*)d_in[0];
    const float* phase = (const float*)d_in[1];
    const float* skill = (const float*)d_in[2];
    const float* p_hat = (const float*)d_in[3];
    const float* u0    = (const float*)d_in[4];
    const float* Wc    = (const float*)d_in[5];
    const float* bc    = (const float*)d_in[6];
    const float* W1    = (const float*)d_in[7];
    const float* b1    = (const float*)d_in[8];
    const float* W2    = (const float*)d_in[9];
    const float* b2    = (const float*)d_in[10];
    const float* W3    = (const float*)d_in[11];
    const float* b3    = (const float*)d_in[12];
    const float* Wd    = (const float*)d_in[13];
    const float* bd    = (const float*)d_in[14];
    float* out = (float*)d_out;

    float *u, *uadd, *tauv, *part;
    int* flag;
    fp16 *cpre, *x, *cnd, *uf, *h1, *h2;
    fp16 *wct, *w1ut, *w1ct, *w2t, *w3t, *wdt;
    cudaGetSymbolAddress((void**)&cpre, g_cpre);
    cudaGetSymbolAddress((void**)&u,    g_u);
    cudaGetSymbolAddress((void**)&uadd, g_uadd);
    cudaGetSymbolAddress((void**)&tauv, g_tauv);
    cudaGetSymbolAddress((void**)&part, g_part);
    cudaGetSymbolAddress((void**)&flag, g_flag);
    cudaGetSymbolAddress((void**)&x,   g_x);
    cudaGetSymbolAddress((void**)&cnd, g_c);
    cudaGetSymbolAddress((void**)&uf,  g_uf);
    cudaGetSymbolAddress((void**)&h1,  g_h1);
    cudaGetSymbolAddress((void**)&h2,  g_h2);
    cudaGetSymbolAddress((void**)&wct,  g_wct);
    cudaGetSymbolAddress((void**)&w1ut, g_w1ut);
    cudaGetSymbolAddress((void**)&w1ct, g_w1ct);
    cudaGetSymbolAddress((void**)&w2t,  g_w2t);
    cudaGetSymbolAddress((void**)&w3t,  g_w3t);
    cudaGetSymbolAddress((void**)&wdt,  g_wdt);

    constexpr int SMEM = NSTG * STG;   // 3 * 36864 = 110592  (2 CTAs/SM fits)
    cudaFuncSetAttribute(mma_gemm<0>, cudaFuncAttributeMaxDynamicSharedMemorySize, SMEM);
    cudaFuncSetAttribute(mma_gemm<1>, cudaFuncAttributeMaxDynamicSharedMemorySize, SMEM);
    cudaFuncSetAttribute(mma_gemm<2>, cudaFuncAttributeMaxDynamicSharedMemorySize, SMEM);
    cudaFuncSetAttribute(mma_gemm<3>, cudaFuncAttributeMaxDynamicSharedMemorySize, SMEM);
    cudaFuncSetAttribute(mma_gemm<6>, cudaFuncAttributeMaxDynamicSharedMemorySize, SMEM);
    cudaFuncSetAttribute(mma_gemm<7>, cudaFuncAttributeMaxDynamicSharedMemorySize, SMEM);

    // ---- launch 0: fused misc setup (also zeroes handoff flags) ----
    combo_setup<<<(BB * COND_IN + 255) / 256, 256>>>(
        fused, phase, skill, u0, p_hat, b3, W1, x, u, uf, uadd, tauv, flag);

    // ---- launch 1: all weight transposes ----
    {
        TJobs J;
        J.j[0] = { Wc, wct, 0, 0, FUSION, COND_IN, COND_IN, FUSION, 32, 38, 32 * 38 };
        J.j[1] = { W1, w1ut, (long long)1537 * 1024, (long long)1024 * 512,
                   1024, LATENT, 512, 1024, 32, 16, 32 * 16 * NEXP };
        J.j[2] = { W1 + (size_t)512 * 1024, w1ct, (long long)1537 * 1024, (long long)1024 * 1024,
                   1024, FUSION, 1024, 1024, 32, 32, 32 * 32 * NEXP };
        J.j[3] = { W2, w2t, (long long)1 << 20, (long long)1 << 20,
                   1024, HID, 1024, 1024, 32, 32, 32 * 32 * NEXP };
        J.j[4] = { W3, w3t, (long long)1024 * 512, (long long)1024,
                   512, KH, 1024, 512, 16, 32, 16 * 32 * NEXP };
        J.j[5] = { Wd, wdt, 0, 0, LATENT, LATENT, 512, 512, 16, 16, 16 * 16 };
        int total = 0;
        for (int k = 0; k < 6; k++) total += J.j[k].ntiles;
        tconv_all<<<total, dim3(32, 8)>>>(J);
    }

    // cond = xcat @ Wc + bc -> fp16            (M=4096, N=1024, K=1216)
    mma_gemm<1><<<dim3(FUSION / 128, BB / 128), 256, SMEM>>>(
        x, COND_IN, wct, COND_IN, COND_IN,
        nullptr, 0, cnd, FUSION, bc, nullptr, 0, nullptr, 0.f,
        nullptr, nullptr, nullptr, 0);

    // cpre = fp16(cond @ W1c + b1)             (N=8192, K=1024)
    mma_gemm<1><<<dim3(KH / 128, BB / 128), 256, SMEM>>>(
        cnd, FUSION, w1ct, FUSION, FUSION,
        nullptr, 0, cpre, KH, b1, nullptr, 0, nullptr, 0.f,
        nullptr, nullptr, nullptr, 0);

    // ---- flow loop ----
    for (int i = 0; i < 8; i++) {
        float tau = (float)i * DT;
        // h1 = silu(u @ w1u + cpre + tau*tauv) (N=8192, K=512)
        mma_gemm<2><<<dim3(KH / 128, BB / 128), 256, SMEM>>>(
            uf, LATENT, w1ut, LATENT, LATENT,
            nullptr, 0, h1, KH, nullptr, cpre, KH, tauv, tau,
            nullptr, nullptr, nullptr, 0);
        // h2 = silu(h1_k @ W2_k + b2_k) * gate (N=1024/expert, K=1024)
        mma_gemm<3><<<dim3(HID / 128, BB / 128, NEXP), 256, SMEM>>>(
            h1, KH, w2t, HID, HID,
            nullptr, 0, h2, KH, b2, nullptr, 0, p_hat, 0.f,
            nullptr, nullptr, nullptr, 0);
        // fused split-K u-update: u += DT*(h2@W3) + uadd ; uf = fp16(u)
        mma_gemm<7><<<dim3(LATENT / 128, BB / 128, 2), 256, SMEM>>>(
            h2, KH, w3t, KH, KH / 2,
            u, LATENT, uf, LATENT, nullptr, nullptr, 0, nullptr, 0.f,
            part, uadd, flag, i + 1);
    }

    // decode (+ u copy): out[:2M] = u @ Wd + bd ; out[2M:] = u
    if (out_size >= 2 * BB * LATENT) {
        mma_gemm<6><<<dim3(LATENT / 128, BB / 128), 256, SMEM>>>(
            uf, LATENT, wdt, LATENT, LATENT,
            out, LATENT, nullptr, 0, bd, nullptr, 0, u, 0.f,
            nullptr, nullptr, nullptr, 0);
    } else {
        mma_gemm<0><<<dim3(LATENT / 128, BB / 128), 256, SMEM>>>(
            uf, LATENT, wdt, LATENT, LATENT,
            out, LATENT, nullptr, 0, bd, nullptr, 0, nullptr, 0.f,
            nullptr, nullptr, nullptr, 0);
    }
}

// round 17
// speedup vs baseline: 1.0075x; 1.0075x over previous
#include <cuda_runtime.h>
#include <cuda_fp16.h>
#include <cstdint>
#include <cstddef>

// ---------------------------------------------------------------------------
// FlowActionHeadPACE — round 16: best-known config (128x128 tile, 256 thr,
// BK=64, NSTG=3, 2 CTAs/SM, split-K h3 + finalize) with compile-time K
// (KDIM template) to cut mainloop integer/branch issue overhead.
//
//   cond   = concat(...) @ Wc + bc                        (once -> fp16)
//   cpre   = fp16(cond @ W1_c + b1)                       (once)
//   uadd   = dt * (p_hat @ b3)                            (once)
//   step i: h1 = silu(u @ W1_u + cpre + tau*w1_tau)       -> fp16
//           h2 = silu(h1_k @ W2_k + b2_k) * gate          -> fp16
//           P[z] = h2 @ W3 (K split in 2)                 -> fp32 partials
//           u += dt*(P0+P1) + uadd ; uf = fp16(u)         (finalize)
//   out = [u @ Wd + bd , u]                               (one kernel)
// ---------------------------------------------------------------------------

#define BB      4096
#define FUSION  1024
#define COND_IN 1216
#define LATENT  512
#define NEXP    8
#define HID     1024
#define KH      8192
#define DT      0.125f

typedef __half fp16;

// ---------------- device scratch ----------------
__device__ float g_u   [(size_t)BB * LATENT];
__device__ float g_uadd[(size_t)BB * LATENT];
__device__ float g_tauv[KH];
__device__ float g_part[2 * (size_t)BB * LATENT];   // split-K partials

__device__ __align__(16) fp16 g_cpre[(size_t)BB * KH];
__device__ __align__(16) fp16 g_x  [(size_t)BB * COND_IN];
__device__ __align__(16) fp16 g_c  [(size_t)BB * FUSION];
__device__ __align__(16) fp16 g_uf [(size_t)BB * LATENT];
__device__ __align__(16) fp16 g_h1 [(size_t)BB * KH];
__device__ __align__(16) fp16 g_h2 [(size_t)BB * KH];

__device__ __align__(16) fp16 g_wct [(size_t)FUSION * COND_IN];
__device__ __align__(16) fp16 g_w1ut[(size_t)KH * LATENT];
__device__ __align__(16) fp16 g_w1ct[(size_t)KH * FUSION];
__device__ __align__(16) fp16 g_w2t [(size_t)NEXP * HID * HID];
__device__ __align__(16) fp16 g_w3t [(size_t)LATENT * KH];
__device__ __align__(16) fp16 g_wdt [(size_t)LATENT * LATENT];

// ---------------- helpers ----------------
__device__ __forceinline__ uint32_t smem_u32(const void* p) {
    uint32_t a;
    asm("{ .reg .u64 t; cvta.to.shared.u64 t, %1; cvt.u32.u64 %0, t; }" : "=r"(a) : "l"(p));
    return a;
}
__device__ __forceinline__ void cp_async16(uint32_t dst, const void* src) {
    asm volatile("cp.async.cg.shared.global [%0], [%1], 16;" :: "r"(dst), "l"(src));
}
#define CP_COMMIT() asm volatile("cp.async.commit_group;" ::: "memory")
#define CP_WAIT2()  asm volatile("cp.async.wait_group 2;" ::: "memory")

#define LDM4(r0, r1, r2, r3, addr)                                             \
    asm volatile("ldmatrix.sync.aligned.m8n8.x4.shared.b16 {%0,%1,%2,%3}, [%4];" \
        : "=r"(r0), "=r"(r1), "=r"(r2), "=r"(r3) : "r"(addr))

#define MMA16816(d, a, b0, b1)                                                \
    asm volatile("mma.sync.aligned.m16n8k16.row.col.f32.f16.f16.f32 "         \
        "{%0,%1,%2,%3}, {%4,%5,%6,%7}, {%8,%9}, {%0,%1,%2,%3};"               \
        : "+f"((d)[0]), "+f"((d)[1]), "+f"((d)[2]), "+f"((d)[3])              \
        : "r"((a)[0]), "r"((a)[1]), "r"((a)[2]), "r"((a)[3]),                 \
          "r"(b0), "r"(b1))

// ---------------------------------------------------------------------------
// HMMA GEMM: C(128x128) = epi( A[M,KDIM] @ B[N,KDIM]^T ), fp16 in, fp32 acc.
// 8 warps 4(M)x2(N); warp tile 32x64; BK=64; 3-stage cp.async; 2 CTAs/SM.
// KDIM is compile-time -> constexpr chunk count, constant-folded staging.
// MODE 0: Cf = acc + bias[c]                              (fp32 store)
// MODE 1: Ca = fp16(acc + bias[c])                        (cond / cpre)
// MODE 2: Ca = fp16(silu(acc + addm(fp16) + s1*vecc[c]))  (h1)
// MODE 3: Ca = fp16(silu(acc + bias[c]) * vecc[r*8+ke])   (h2, z=expert)
// MODE 5: Cf = acc  (split-K partial; z selects K half and partial buffer)
// MODE 6: Cf = acc + bias[c]; Cf[(BB+r)*ldc+cg] = vecc[...] (decode+copy)
// ---------------------------------------------------------------------------
#define ROWB  144                 // bytes per smem row (64 fp16 + 16B pad)
#define PLANE (128 * ROWB)        // 18432 B
#define STG   (2 * PLANE)         // A, B = 36864 B
#define NSTG  3

template <int MODE, int KDIM>
__global__ void __launch_bounds__(256, 2)
mma_gemm(const fp16* __restrict__ A, int lda,
         const fp16* __restrict__ B, int ldb,
         float* __restrict__ Cf, int ldc,
         fp16* __restrict__ Ca, int ldc2,
         const float* __restrict__ bias,
         const fp16* __restrict__ addm, int addld,
         const float* __restrict__ vecc, float s1) {
    extern __shared__ char smem[];
    const uint32_t sbase = smem_u32(smem);
    const int tid  = threadIdx.x;
    const int wid  = tid >> 5;
    const int lane = tid & 31;
    const int wm   = wid >> 1;          // 0..3  (M)
    const int wc   = wid & 1;           // 0..1  (N)
    const int brow = blockIdx.y * 128;
    const int bcol = blockIdx.x * 128;

    int kexp = 0;
    if (MODE == 3) {
        kexp = blockIdx.z;
        A  += kexp * HID;
        B  += (size_t)kexp * HID * HID;
        Ca += kexp * HID;
        bias += kexp * HID;
    }
    if (MODE == 5) {
        const int z = blockIdx.z;
        A  += (size_t)z * KDIM;                   // shift K window (lda = full K)
        B  += (size_t)z * KDIM;
        Cf += (size_t)z * ((size_t)BB * LATENT);  // partial buffer z
    }

    const fp16* Ap = A + (size_t)brow * lda;
    const fp16* Bp = B + (size_t)bcol * ldb;

    constexpr int NC = KDIM >> 6;       // BK = 64, compile-time

    auto load_chunk = [&](int c, int stage) {
        const uint32_t st = sbase + stage * STG;
        const int k0 = c << 6;
#pragma unroll
        for (int it = 0; it < 4; it++) {
            int id  = tid + it * 256;   // 0..1023
            int row = id >> 3;
            int seg = id & 7;
            uint32_t dst = st + row * ROWB + seg * 16;
            cp_async16(dst,         Ap + (size_t)row * lda + k0 + seg * 8);
            cp_async16(dst + PLANE, Bp + (size_t)row * ldb + k0 + seg * 8);
        }
        CP_COMMIT();
    };

    float acc[2][8][4];
#pragma unroll
    for (int im = 0; im < 2; im++)
#pragma unroll
        for (int jb = 0; jb < 8; jb++)
#pragma unroll
            for (int q = 0; q < 4; q++) acc[im][jb][q] = 0.f;

    load_chunk(0, 0);
    if (NC > 1) load_chunk(1, 1);
    if (NC > 2) load_chunk(2, 2);

    const int lrow = lane & 15;          // ldmatrix row within 16
    const int lkhi = (lane >> 4) * 8;    // k offset 0/8

#pragma unroll 2
    for (int c = 0; c < NC; c++) {
        const int stage = c % NSTG;
        CP_WAIT2();
        __syncthreads();
        const uint32_t st = sbase + stage * STG;
        const uint32_t sA = st;
        const uint32_t sB = st + PLANE;

#pragma unroll
        for (int kk = 0; kk < 64; kk += 16) {
            uint32_t a[2][4];
#pragma unroll
            for (int im = 0; im < 2; im++) {
                uint32_t ad = sA + (wm * 32 + im * 16 + lrow) * ROWB + (kk + lkhi) * 2;
                LDM4(a[im][0], a[im][1], a[im][2], a[im][3], ad);
            }
#pragma unroll
            for (int jb2 = 0; jb2 < 4; jb2++) {
                uint32_t nrow = sB + (wc * 64 + jb2 * 16 + lrow) * ROWB + (kk + lkhi) * 2;
                uint32_t b0, b1, b2, b3;
                LDM4(b0, b1, b2, b3, nrow);
#pragma unroll
                for (int im = 0; im < 2; im++) {
                    MMA16816(acc[im][jb2 * 2 + 0], a[im], b0, b2);
                    MMA16816(acc[im][jb2 * 2 + 1], a[im], b1, b3);
                }
            }
        }
        __syncthreads();
        if (c + 3 < NC) load_chunk(c + 3, stage);
    }

    // ---- epilogue ----
    const int lr  = lane >> 2;
    const int lc2 = (lane & 3) * 2;
#pragma unroll
    for (int im = 0; im < 2; im++) {
#pragma unroll
        for (int half = 0; half < 2; half++) {
            const int r = brow + wm * 32 + im * 16 + lr + half * 8;
#pragma unroll
            for (int jb = 0; jb < 8; jb++) {
                const int cg = bcol + wc * 64 + jb * 8 + lc2;
                float a0 = acc[im][jb][half * 2 + 0];
                float a1 = acc[im][jb][half * 2 + 1];
                float v0, v1;
                if (MODE == 0 || MODE == 6) {
                    v0 = a0 + bias[cg]; v1 = a1 + bias[cg + 1];
                    *(float2*)(Cf + (size_t)r * ldc + cg) = make_float2(v0, v1);
                    if (MODE == 6) {
                        float2 uv = *(const float2*)(vecc + (size_t)r * ldc + cg);
                        *(float2*)(Cf + (size_t)(BB + r) * ldc + cg) = uv;
                    }
                } else if (MODE == 5) {
                    *(float2*)(Cf + (size_t)r * ldc + cg) = make_float2(a0, a1);
                } else {
                    if (MODE == 1) {
                        v0 = a0 + bias[cg]; v1 = a1 + bias[cg + 1];
                    } else if (MODE == 2) {
                        __half2 ah2 = *(const __half2*)(addm + (size_t)r * addld + cg);
                        float2 ad = __half22float2(ah2);
                        v0 = a0 + ad.x + s1 * vecc[cg];
                        v1 = a1 + ad.y + s1 * vecc[cg + 1];
                        v0 = v0 / (1.f + __expf(-v0));
                        v1 = v1 / (1.f + __expf(-v1));
                    } else {  // MODE 3
                        v0 = a0 + bias[cg]; v1 = a1 + bias[cg + 1];
                        v0 = v0 / (1.f + __expf(-v0));
                        v1 = v1 / (1.f + __expf(-v1));
                        float gt = vecc[r * 8 + kexp];
                        v0 *= gt; v1 *= gt;
                    }
                    *(__half2*)(Ca + (size_t)r * ldc2 + cg) =
                        __halves2half2(__float2half_rn(v0), __float2half_rn(v1));
                }
            }
        }
    }
}

// ---------------------------------------------------------------------------
// setup / epilogue kernels
// ---------------------------------------------------------------------------
__global__ void combo_setup(const float* __restrict__ fo,
                            const float* __restrict__ pe,
                            const float* __restrict__ sl,
                            const float* __restrict__ u0,
                            const float* __restrict__ p,
                            const float* __restrict__ b3,
                            const float* __restrict__ W1,
                            fp16* __restrict__ x,
                            float* __restrict__ u, fp16* __restrict__ uf,
                            float* __restrict__ uadd,
                            float* __restrict__ tv) {
    int i = blockIdx.x * blockDim.x + threadIdx.x;
    if (i < BB * COND_IN) {
        int b = i / COND_IN, j = i - b * COND_IN;
        float v;
        if (j < 1024)       v = fo[b * 1024 + j];
        else if (j < 1152)  v = pe[b * 128 + (j - 1024)];
        else                v = sl[b * 64 + (j - 1152)];
        x[i] = __float2half_rn(v);
    }
    if (i < BB * LATENT) {
        int b = i >> 9, d = i & 511;
        float v = u0[i];
        u[i] = v;
        uf[i] = __float2half_rn(v);
        float s = 0.f;
#pragma unroll
        for (int k = 0; k < NEXP; k++) s += p[b * 8 + k] * b3[k * 512 + d];
        uadd[i] = DT * s;
    }
    if (i < KH) {
        int ke = i >> 10, hcol = i & 1023;
        tv[i] = W1[((size_t)ke * 1537 + 1536) * 1024 + hcol];
    }
}

__global__ void finalize_u(const float* __restrict__ P,
                           float* __restrict__ u, fp16* __restrict__ uf,
                           const float* __restrict__ uadd) {
    int i = blockIdx.x * blockDim.x + threadIdx.x;
    if (i >= BB * LATENT) return;
    float v = u[i] + DT * (P[i] + P[i + (size_t)BB * LATENT]) + uadd[i];
    u[i] = v;
    uf[i] = __float2half_rn(v);
}

struct TJob {
    const float* in;
    fp16* out;
    long long in_es, out_es;
    int in_ld, out_ld, rows, cols, tx, ty, ntiles;
};
struct TJobs { TJob j[6]; };

__global__ void tconv_all(TJobs J) {
    __shared__ float t[32][33];
    int f = blockIdx.x;
    const TJob* job = nullptr;
    int iz = 0, ix = 0, iy = 0;
#pragma unroll
    for (int jj = 0; jj < 6; jj++) {
        if (job == nullptr) {
            if (f < J.j[jj].ntiles) {
                job = &J.j[jj];
                int per = job->tx * job->ty;
                iz = f / per;
                int rem = f - iz * per;
                ix = rem % job->tx;
                iy = rem / job->tx;
            } else {
                f -= J.j[jj].ntiles;
            }
        }
    }
    const float* in = job->in + (size_t)iz * job->in_es;
    fp16* out = job->out + (size_t)iz * job->out_es;
    const int r0 = iy * 32, c0 = ix * 32;
    const int tx = threadIdx.x, ty = threadIdx.y;      // 32 x 8
#pragma unroll
    for (int i = 0; i < 32; i += 8) {
        int r = r0 + ty + i, c = c0 + tx;
        if (r < job->rows && c < job->cols) t[ty + i][tx] = in[(size_t)r * job->in_ld + c];
    }
    __syncthreads();
#pragma unroll
    for (int i = 0; i < 32; i += 8) {
        int c = c0 + ty + i, r = r0 + tx;
        if (c < job->cols && r < job->rows)
            out[(size_t)c * job->out_ld + r] = __float2half_rn(t[tx][ty + i]);
    }
}

// ---------------------------------------------------------------------------
extern "C" void kernel_launch(void* const* d_in, const int* in_sizes, int n_in,
                              void* d_out, int out_size) {
    const float* fused = (const float*)d_in[0];
    const float* phase = (const float*)d_in[1];
    const float* skill = (const float*)d_in[2];
    const float* p_hat = (const float*)d_in[3];
    const float* u0    = (const float*)d_in[4];
    const float* Wc    = (const float*)d_in[5];
    const float* bc    = (const float*)d_in[6];
    const float* W1    = (const float*)d_in[7];
    const float* b1    = (const float*)d_in[8];
    const float* W2    = (const float*)d_in[9];
    const float* b2    = (const float*)d_in[10];
    const float* W3    = (const float*)d_in[11];
    const float* b3    = (const float*)d_in[12];
    const float* Wd    = (const float*)d_in[13];
    const float* bd    = (const float*)d_in[14];
    float* out = (float*)d_out;

    float *u, *uadd, *tauv, *part;
    fp16 *cpre, *x, *cnd, *uf, *h1, *h2;
    fp16 *wct, *w1ut, *w1ct, *w2t, *w3t, *wdt;
    cudaGetSymbolAddress((void**)&cpre, g_cpre);
    cudaGetSymbolAddress((void**)&u,    g_u);
    cudaGetSymbolAddress((void**)&uadd, g_uadd);
    cudaGetSymbolAddress((void**)&tauv, g_tauv);
    cudaGetSymbolAddress((void**)&part, g_part);
    cudaGetSymbolAddress((void**)&x,   g_x);
    cudaGetSymbolAddress((void**)&cnd, g_c);
    cudaGetSymbolAddress((void**)&uf,  g_uf);
    cudaGetSymbolAddress((void**)&h1,  g_h1);
    cudaGetSymbolAddress((void**)&h2,  g_h2);
    cudaGetSymbolAddress((void**)&wct,  g_wct);
    cudaGetSymbolAddress((void**)&w1ut, g_w1ut);
    cudaGetSymbolAddress((void**)&w1ct, g_w1ct);
    cudaGetSymbolAddress((void**)&w2t,  g_w2t);
    cudaGetSymbolAddress((void**)&w3t,  g_w3t);
    cudaGetSymbolAddress((void**)&wdt,  g_wdt);

    constexpr int SMEM = NSTG * STG;   // 3 * 36864 = 110592  (2 CTAs/SM fits)
    cudaFuncSetAttribute(mma_gemm<1, COND_IN>, cudaFuncAttributeMaxDynamicSharedMemorySize, SMEM);
    cudaFuncSetAttribute(mma_gemm<1, FUSION>,  cudaFuncAttributeMaxDynamicSharedMemorySize, SMEM);
    cudaFuncSetAttribute(mma_gemm<2, LATENT>,  cudaFuncAttributeMaxDynamicSharedMemorySize, SMEM);
    cudaFuncSetAttribute(mma_gemm<3, HID>,     cudaFuncAttributeMaxDynamicSharedMemorySize, SMEM);
    cudaFuncSetAttribute(mma_gemm<5, KH / 2>,  cudaFuncAttributeMaxDynamicSharedMemorySize, SMEM);
    cudaFuncSetAttribute(mma_gemm<6, LATENT>,  cudaFuncAttributeMaxDynamicSharedMemorySize, SMEM);
    cudaFuncSetAttribute(mma_gemm<0, LATENT>,  cudaFuncAttributeMaxDynamicSharedMemorySize, SMEM);

    // ---- launch 0: fused misc setup ----
    combo_setup<<<(BB * COND_IN + 255) / 256, 256>>>(
        fused, phase, skill, u0, p_hat, b3, W1, x, u, uf, uadd, tauv);

    // ---- launch 1: all weight transposes ----
    {
        TJobs J;
        J.j[0] = { Wc, wct, 0, 0, FUSION, COND_IN, COND_IN, FUSION, 32, 38, 32 * 38 };
        J.j[1] = { W1, w1ut, (long long)1537 * 1024, (long long)1024 * 512,
                   1024, LATENT, 512, 1024, 32, 16, 32 * 16 * NEXP };
        J.j[2] = { W1 + (size_t)512 * 1024, w1ct, (long long)1537 * 1024, (long long)1024 * 1024,
                   1024, FUSION, 1024, 1024, 32, 32, 32 * 32 * NEXP };
        J.j[3] = { W2, w2t, (long long)1 << 20, (long long)1 << 20,
                   1024, HID, 1024, 1024, 32, 32, 32 * 32 * NEXP };
        J.j[4] = { W3, w3t, (long long)1024 * 512, (long long)1024,
                   512, KH, 1024, 512, 16, 32, 16 * 32 * NEXP };
        J.j[5] = { Wd, wdt, 0, 0, LATENT, LATENT, 512, 512, 16, 16, 16 * 16 };
        int total = 0;
        for (int k = 0; k < 6; k++) total += J.j[k].ntiles;
        tconv_all<<<total, dim3(32, 8)>>>(J);
    }

    // cond = xcat @ Wc + bc -> fp16            (M=4096, N=1024, K=1216)
    mma_gemm<1, COND_IN><<<dim3(FUSION / 128, BB / 128), 256, SMEM>>>(
        x, COND_IN, wct, COND_IN,
        nullptr, 0, cnd, FUSION, bc, nullptr, 0, nullptr, 0.f);

    // cpre = fp16(cond @ W1c + b1)             (N=8192, K=1024)
    mma_gemm<1, FUSION><<<dim3(KH / 128, BB / 128), 256, SMEM>>>(
        cnd, FUSION, w1ct, FUSION,
        nullptr, 0, cpre, KH, b1, nullptr, 0, nullptr, 0.f);

    // ---- flow loop ----
    for (int i = 0; i < 8; i++) {
        float tau = (float)i * DT;
        // h1 = silu(u @ w1u + cpre + tau*tauv) (N=8192, K=512)
        mma_gemm<2, LATENT><<<dim3(KH / 128, BB / 128), 256, SMEM>>>(
            uf, LATENT, w1ut, LATENT,
            nullptr, 0, h1, KH, nullptr, cpre, KH, tauv, tau);
        // h2 = silu(h1_k @ W2_k + b2_k) * gate (N=1024/expert, K=1024)
        mma_gemm<3, HID><<<dim3(HID / 128, BB / 128, NEXP), 256, SMEM>>>(
            h1, KH, w2t, HID,
            nullptr, 0, h2, KH, b2, nullptr, 0, p_hat, 0.f);
        // P[z] = h2 @ W3 slice (split-K=2)     (N=512, K=4096 each)
        mma_gemm<5, KH / 2><<<dim3(LATENT / 128, BB / 128, 2), 256, SMEM>>>(
            h2, KH, w3t, KH,
            part, LATENT, nullptr, 0, nullptr, nullptr, 0, nullptr, 0.f);
        // u += DT*(P0+P1) + uadd ; uf = fp16(u)
        finalize_u<<<(BB * LATENT + 255) / 256, 256>>>(part, u, uf, uadd);
    }

    // decode (+ u copy): out[:2M] = u @ Wd + bd ; out[2M:] = u
    if (out_size >= 2 * BB * LATENT) {
        mma_gemm<6, LATENT><<<dim3(LATENT / 128, BB / 128), 256, SMEM>>>(
            uf, LATENT, wdt, LATENT,
            out, LATENT, nullptr, 0, bd, nullptr, 0, u, 0.f);
    } else {
        mma_gemm<0, LATENT><<<dim3(LATENT / 128, BB / 128), 256, SMEM>>>(
            uf, LATENT, wdt, LATENT,
            out, LATENT, nullptr, 0, bd, nullptr, 0, nullptr, 0.f);
    }
}